// round 5
// baseline (speedup 1.0000x reference)
#include <cuda_runtime.h>

#define BB 256
#define TT 512
#define EMBD 64
#define HID 128

__device__ float g_pre1[(long)TT * BB * HID];   // [t][b][j], 64 MB
__device__ float g_h2[BB * HID];

// tanh(x) = 1 - 2/(e^{2x}+1), via MUFU ex2/rcp. |err| ~1e-7. Clamp for safety.
__device__ __forceinline__ float fast_tanh(float x) {
    float xc = fminf(fmaxf(x, -20.f), 20.f);
    float e;
    asm("ex2.approx.f32 %0, %1;" : "=f"(e) : "f"(xc * 2.8853900817779268f)); // 2*log2(e)
    float r;
    asm("rcp.approx.f32 %0, %1;" : "=f"(r) : "f"(e + 1.f));
    return fmaf(-2.f, r, 1.f);
}

// ---------------------------------------------------------------------------
// Kernel 1: pre1[t][b][j] = dot(emb[x[b,t]], Wih1[j]) + b_ih1[j] + b_hh1[j]
// (identical to the 644us R1 version)
// ---------------------------------------------------------------------------
__global__ __launch_bounds__(128) void k_pre1(
    const int* __restrict__ x, const float* __restrict__ emb,
    const float* __restrict__ Wih1, const float* __restrict__ bih1,
    const float* __restrict__ bhh1)
{
    __shared__ __align__(16) float shW[HID * 68];
    __shared__ __align__(16) float4 shE[8 * 16];
    __shared__ int shX[8];

    const int tid = threadIdx.x;   // output feature j

    for (int it = 0; it < 64; ++it) {
        int f = it * 128 + tid;
        int j = f >> 6, k = f & 63;
        shW[j * 68 + k] = Wih1[f];
    }
    __syncthreads();

    float Wr[64];
#pragma unroll
    for (int i = 0; i < 64; ++i) Wr[i] = shW[tid * 68 + i];
    const float bb = bih1[tid] + bhh1[tid];

    const int base = blockIdx.x * 256;              // 256 (b,t) rows per block
    const float4* __restrict__ e4 = (const float4*)emb;

    for (int it = 0; it < 32; ++it) {
        const int rid0 = base + it * 8;             // rid = t*256 + b
        if (tid < 8) {
            int rid = rid0 + tid;
            int t = rid >> 8, b = rid & 255;
            shX[tid] = x[b * TT + t];
        }
        __syncthreads();
        {
            int r = tid >> 4, f = tid & 15;
            shE[r * 16 + f] = e4[(long)shX[r] * 16 + f];
        }
        __syncthreads();

        float acc[8];
#pragma unroll
        for (int r = 0; r < 8; ++r) acc[r] = bb;
#pragma unroll
        for (int k4 = 0; k4 < 16; ++k4) {
#pragma unroll
            for (int r = 0; r < 8; ++r) {
                float4 e = shE[r * 16 + k4];
                acc[r] = fmaf(Wr[4 * k4 + 0], e.x, acc[r]);
                acc[r] = fmaf(Wr[4 * k4 + 1], e.y, acc[r]);
                acc[r] = fmaf(Wr[4 * k4 + 2], e.z, acc[r]);
                acc[r] = fmaf(Wr[4 * k4 + 3], e.w, acc[r]);
            }
        }
#pragma unroll
        for (int r = 0; r < 8; ++r)
            g_pre1[(long)(rid0 + r) * HID + tid] = acc[r];
        __syncthreads();
    }
}

// ---------------------------------------------------------------------------
// Kernel 2: fused two-layer scan (R1 skeleton + rebalanced phases + fast tanh).
// 128 blocks x 256 threads; block handles rows b0,b0+1.
// Thread (j = tid&127, p = tid>>7) holds k-half rows of W_hh1/W_ih2/W_hh2.
//   A: partials of W_hh1*h1_old AND W_hh2*h2_old (both rows)   [256 FMA/thr]
//   B: h1_new = tanh(pre + sumA);  d2 = bb2 + sumB (kept in reg)
//   C: partials of W_ih2*h1_new (both rows)                     [128 FMA/thr]
//   D: h2_new = tanh(d2 + sumC)
// ---------------------------------------------------------------------------
__global__ __launch_bounds__(256, 1) void k_scan(
    const float* __restrict__ Whh1, const float* __restrict__ Wih2,
    const float* __restrict__ Whh2, const float* __restrict__ bih2,
    const float* __restrict__ bhh2)
{
    __shared__ __align__(16) float sh_h1[2][HID];
    __shared__ __align__(16) float sh_h2[2][HID];
    __shared__ __align__(16) float sh_pA[2][2][HID];   // [half][row][j]
    __shared__ __align__(16) float sh_pB[2][2][HID];   // [half][row][j]

    const int tid = threadIdx.x;
    const int j = tid & 127;
    const int p = tid >> 7;            // k-half (uniform per warp)
    const int b0 = blockIdx.x * 2;

    float W1r[64], Wi2r[64], W2r[64];
    {
        const float* w1 = Whh1 + j * HID + p * 64;
        const float* wi = Wih2 + j * HID + p * 64;
        const float* w2 = Whh2 + j * HID + p * 64;
#pragma unroll
        for (int i = 0; i < 64; ++i) { W1r[i] = w1[i]; Wi2r[i] = wi[i]; W2r[i] = w2[i]; }
    }
    const float bb2 = bih2[j] + bhh2[j];

    sh_h1[p][j] = 0.f;
    sh_h2[p][j] = 0.f;
    __syncthreads();

    // Own combine row = p; pre1 stream for row b0+p, feature j.
    const float* preBase = g_pre1 + (long)(b0 + p) * HID + j;
    float pre_r = preBase[0];
    float d2 = 0.f;

    const float4* h10p = (const float4*)&sh_h1[0][p * 64];
    const float4* h11p = (const float4*)&sh_h1[1][p * 64];
    const float4* h20p = (const float4*)&sh_h2[0][p * 64];
    const float4* h21p = (const float4*)&sh_h2[1][p * 64];

    for (int t = 0; t < TT; ++t) {
        // ---- Phase A: W_hh1*h1_old and W_hh2*h2_old partials, both rows ----
        float a0 = 0.f, a1 = 0.f, e0 = 0.f, e1 = 0.f;
#pragma unroll
        for (int i = 0; i < 16; ++i) {
            float4 u = h10p[i];
            a0 = fmaf(W1r[4 * i + 0], u.x, a0);
            a0 = fmaf(W1r[4 * i + 1], u.y, a0);
            a0 = fmaf(W1r[4 * i + 2], u.z, a0);
            a0 = fmaf(W1r[4 * i + 3], u.w, a0);
            float4 v = h11p[i];
            a1 = fmaf(W1r[4 * i + 0], v.x, a1);
            a1 = fmaf(W1r[4 * i + 1], v.y, a1);
            a1 = fmaf(W1r[4 * i + 2], v.z, a1);
            a1 = fmaf(W1r[4 * i + 3], v.w, a1);
            float4 g0 = h20p[i];
            e0 = fmaf(W2r[4 * i + 0], g0.x, e0);
            e0 = fmaf(W2r[4 * i + 1], g0.y, e0);
            e0 = fmaf(W2r[4 * i + 2], g0.z, e0);
            e0 = fmaf(W2r[4 * i + 3], g0.w, e0);
            float4 g1 = h21p[i];
            e1 = fmaf(W2r[4 * i + 0], g1.x, e1);
            e1 = fmaf(W2r[4 * i + 1], g1.y, e1);
            e1 = fmaf(W2r[4 * i + 2], g1.z, e1);
            e1 = fmaf(W2r[4 * i + 3], g1.w, e1);
        }
        sh_pA[p][0][j] = a0;
        sh_pA[p][1][j] = a1;
        sh_pB[p][0][j] = e0;
        sh_pB[p][1][j] = e1;
        __syncthreads();

        // ---- Phase B: h1_new for row p; d2 (reg) for row p ----
        {
            float v = pre_r + sh_pA[0][p][j] + sh_pA[1][p][j];
            sh_h1[p][j] = fast_tanh(v);
            d2 = bb2 + sh_pB[0][p][j] + sh_pB[1][p][j];
        }
        if (t + 1 < TT) pre_r = preBase[(long)(t + 1) * BB * HID];
        __syncthreads();

        // ---- Phase C: W_ih2 * h1_new partials, both rows ----
        float c0 = 0.f, c1 = 0.f;
#pragma unroll
        for (int i = 0; i < 16; ++i) {
            float4 u = h10p[i];
            c0 = fmaf(Wi2r[4 * i + 0], u.x, c0);
            c0 = fmaf(Wi2r[4 * i + 1], u.y, c0);
            c0 = fmaf(Wi2r[4 * i + 2], u.z, c0);
            c0 = fmaf(Wi2r[4 * i + 3], u.w, c0);
            float4 v = h11p[i];
            c1 = fmaf(Wi2r[4 * i + 0], v.x, c1);
            c1 = fmaf(Wi2r[4 * i + 1], v.y, c1);
            c1 = fmaf(Wi2r[4 * i + 2], v.z, c1);
            c1 = fmaf(Wi2r[4 * i + 3], v.w, c1);
        }
        sh_pA[p][0][j] = c0;
        sh_pA[p][1][j] = c1;
        __syncthreads();

        // ---- Phase D: h2_new for row p ----
        {
            float v2 = d2 + sh_pA[0][p][j] + sh_pA[1][p][j];
            sh_h2[p][j] = fast_tanh(v2);
        }
        __syncthreads();
    }

    g_h2[(b0 + p) * HID + j] = sh_h2[p][j];
}

// ---------------------------------------------------------------------------
// Kernel 3: epilogue — LN -> proj -> tanh -> LN. One block per batch row.
// ---------------------------------------------------------------------------
__global__ __launch_bounds__(128) void k_epi(
    const float* __restrict__ ln_g, const float* __restrict__ ln_b,
    const float* __restrict__ projW, const float* __restrict__ proj_b,
    const float* __restrict__ on_g, const float* __restrict__ on_b,
    float* __restrict__ out)
{
    __shared__ __align__(16) float sh_rep[HID];
    __shared__ float sh_red[8];

    const int j = threadIdx.x;
    const int b = blockIdx.x;

    float v = g_h2[b * HID + j];

    // LN 1
    float s = v, q = v * v;
#pragma unroll
    for (int o = 16; o; o >>= 1) {
        s += __shfl_xor_sync(0xffffffffu, s, o);
        q += __shfl_xor_sync(0xffffffffu, q, o);
    }
    if ((j & 31) == 0) { sh_red[j >> 5] = s; sh_red[4 + (j >> 5)] = q; }
    __syncthreads();
    s = sh_red[0] + sh_red[1] + sh_red[2] + sh_red[3];
    q = sh_red[4] + sh_red[5] + sh_red[6] + sh_red[7];
    float mu = s * (1.f / HID);
    float var = q * (1.f / HID) - mu * mu;
    float rep = (v - mu) * rsqrtf(var + 1e-5f) * ln_g[j] + ln_b[j];
    sh_rep[j] = rep;
    __syncthreads();

    // proj + tanh
    float acc = proj_b[j];
    const float4* w4 = (const float4*)(projW + j * HID);
    const float4* r4 = (const float4*)sh_rep;
#pragma unroll
    for (int i = 0; i < 32; ++i) {
        float4 w = __ldg(&w4[i]);
        float4 r = r4[i];
        acc = fmaf(w.x, r.x, acc);
        acc = fmaf(w.y, r.y, acc);
        acc = fmaf(w.z, r.z, acc);
        acc = fmaf(w.w, r.w, acc);
    }
    float tv = tanhf(acc);

    // LN 2
    __syncthreads();
    s = tv; q = tv * tv;
#pragma unroll
    for (int o = 16; o; o >>= 1) {
        s += __shfl_xor_sync(0xffffffffu, s, o);
        q += __shfl_xor_sync(0xffffffffu, q, o);
    }
    if ((j & 31) == 0) { sh_red[j >> 5] = s; sh_red[4 + (j >> 5)] = q; }
    __syncthreads();
    s = sh_red[0] + sh_red[1] + sh_red[2] + sh_red[3];
    q = sh_red[4] + sh_red[5] + sh_red[6] + sh_red[7];
    float mu2 = s * (1.f / HID);
    float var2 = q * (1.f / HID) - mu2 * mu2;
    out[b * HID + j] = (tv - mu2) * rsqrtf(var2 + 1e-5f) * on_g[j] + on_b[j];
}

// ---------------------------------------------------------------------------
extern "C" void kernel_launch(void* const* d_in, const int* in_sizes, int n_in,
                              void* d_out, int out_size)
{
    const int*   x     = (const int*)  d_in[0];
    const float* emb   = (const float*)d_in[1];
    const float* Wih1  = (const float*)d_in[2];
    const float* bih1  = (const float*)d_in[3];
    const float* Whh1  = (const float*)d_in[4];
    const float* bhh1  = (const float*)d_in[5];
    const float* Wih2  = (const float*)d_in[6];
    const float* bih2  = (const float*)d_in[7];
    const float* Whh2  = (const float*)d_in[8];
    const float* bhh2  = (const float*)d_in[9];
    const float* ln_g  = (const float*)d_in[10];
    const float* ln_b  = (const float*)d_in[11];
    const float* projW = (const float*)d_in[12];
    const float* projb = (const float*)d_in[13];
    const float* on_g  = (const float*)d_in[14];
    const float* on_b  = (const float*)d_in[15];

    k_pre1<<<512, 128>>>(x, emb, Wih1, bih1, bhh1);
    k_scan<<<128, 256>>>(Whh1, Wih2, Whh2, bih2, bhh2);
    k_epi<<<256, 128>>>(ln_g, ln_b, projW, projb, on_g, on_b, (float*)d_out);
}

// round 6
// speedup vs baseline: 1.1680x; 1.1680x over previous
#include <cuda_runtime.h>

#define BB 256
#define TT 512
#define EMBD 64
#define HID 128

__device__ float g_pre1[(long)TT * BB * HID];   // [t][b][j]
__device__ float g_out1[(long)TT * BB * HID];   // [t][b][j]
__device__ float g_pre2[(long)TT * BB * HID];   // [t][b][j]
__device__ float g_h2[BB * HID];

// tanh(x) = 1 - 2/(e^{2x}+1) via MUFU. |err| ~1e-7.
__device__ __forceinline__ float fast_tanh(float x) {
    float xc = fminf(fmaxf(x, -20.f), 20.f);
    float e;
    asm("ex2.approx.f32 %0, %1;" : "=f"(e) : "f"(xc * 2.8853900817779268f));
    float r;
    asm("rcp.approx.f32 %0, %1;" : "=f"(r) : "f"(e + 1.f));
    return fmaf(-2.f, r, 1.f);
}

// ---------------------------------------------------------------------------
// Kernel 1: pre1[t][b][j] = dot(emb[x[b,t]], Wih1[j]) + b_ih1[j] + b_hh1[j]
// (identical to the proven R1 version)
// ---------------------------------------------------------------------------
__global__ __launch_bounds__(128) void k_pre1(
    const int* __restrict__ x, const float* __restrict__ emb,
    const float* __restrict__ Wih1, const float* __restrict__ bih1,
    const float* __restrict__ bhh1)
{
    __shared__ __align__(16) float shW[HID * 68];
    __shared__ __align__(16) float4 shE[8 * 16];
    __shared__ int shX[8];

    const int tid = threadIdx.x;

    for (int it = 0; it < 64; ++it) {
        int f = it * 128 + tid;
        int j = f >> 6, k = f & 63;
        shW[j * 68 + k] = Wih1[f];
    }
    __syncthreads();

    float Wr[64];
#pragma unroll
    for (int i = 0; i < 64; ++i) Wr[i] = shW[tid * 68 + i];
    const float bb = bih1[tid] + bhh1[tid];

    const int base = blockIdx.x * 256;
    const float4* __restrict__ e4 = (const float4*)emb;

    for (int it = 0; it < 32; ++it) {
        const int rid0 = base + it * 8;             // rid = t*256 + b
        if (tid < 8) {
            int rid = rid0 + tid;
            int t = rid >> 8, b = rid & 255;
            shX[tid] = x[b * TT + t];
        }
        __syncthreads();
        {
            int r = tid >> 4, f = tid & 15;
            shE[r * 16 + f] = e4[(long)shX[r] * 16 + f];
        }
        __syncthreads();

        float acc[8];
#pragma unroll
        for (int r = 0; r < 8; ++r) acc[r] = bb;
#pragma unroll
        for (int k4 = 0; k4 < 16; ++k4) {
#pragma unroll
            for (int r = 0; r < 8; ++r) {
                float4 e = shE[r * 16 + k4];
                acc[r] = fmaf(Wr[4 * k4 + 0], e.x, acc[r]);
                acc[r] = fmaf(Wr[4 * k4 + 1], e.y, acc[r]);
                acc[r] = fmaf(Wr[4 * k4 + 2], e.z, acc[r]);
                acc[r] = fmaf(Wr[4 * k4 + 3], e.w, acc[r]);
            }
        }
#pragma unroll
        for (int r = 0; r < 8; ++r)
            g_pre1[(long)(rid0 + r) * HID + tid] = acc[r];
        __syncthreads();
    }
}

// ---------------------------------------------------------------------------
// Kernel 2: layer-1 scan only. 128 blocks x 256 threads, 2 rows/block.
// Thread (r = tid>>7, j = tid&127) holds FULL W_hh1 row j in registers.
// Full dot per thread => no partial exchange; double-buffered h1 => 1 bar/step.
//   h1_new = tanh(pre1[t] + W_hh1 . h1_old);   out1[t] streamed to gmem.
// ---------------------------------------------------------------------------
__global__ __launch_bounds__(256, 1) void k_scan1(
    const float* __restrict__ Whh1)
{
    __shared__ __align__(16) float h1s[2][2][HID];   // [buf][row][j]

    const int tid = threadIdx.x;
    const int r = tid >> 7;
    const int j = tid & 127;
    const int b0 = blockIdx.x * 2;
    const int b = b0 + r;

    float W[128];
    {
        const float4* w4 = (const float4*)(Whh1 + j * HID);
#pragma unroll
        for (int i = 0; i < 32; ++i) {
            float4 a = w4[i];
            W[4 * i] = a.x; W[4 * i + 1] = a.y; W[4 * i + 2] = a.z; W[4 * i + 3] = a.w;
        }
    }

    h1s[0][r][j] = 0.f;
    h1s[1][r][j] = 0.f;
    __syncthreads();

    const float* preBase = g_pre1 + (long)b * HID + j;
    float* outBase = g_out1 + (long)b * HID + j;
    float pre_r = preBase[0];

    for (int t = 0; t < TT; ++t) {
        const int cur = t & 1, nxt = cur ^ 1;
        const float4* h = (const float4*)&h1s[cur][r][0];

        float acc = pre_r;
#pragma unroll
        for (int i = 0; i < 32; ++i) {
            float4 u = h[i];
            acc = fmaf(W[4 * i + 0], u.x, acc);
            acc = fmaf(W[4 * i + 1], u.y, acc);
            acc = fmaf(W[4 * i + 2], u.z, acc);
            acc = fmaf(W[4 * i + 3], u.w, acc);
        }
        float h1n = fast_tanh(acc);
        h1s[nxt][r][j] = h1n;
        outBase[(long)t * BB * HID] = h1n;
        if (t + 1 < TT) pre_r = preBase[(long)(t + 1) * BB * HID];
        __syncthreads();
    }
}

// ---------------------------------------------------------------------------
// Kernel 3: pre2[rid][j] = dot(out1[rid], Wih2[j]) + b_ih2[j] + b_hh2[j]
// rid = t*BB + b.  512 blocks x 256 threads; two independent 128-thread
// groups per block, each staging 8 rows at a time. Thread j holds the full
// Wih2 row j in registers.
// ---------------------------------------------------------------------------
__global__ __launch_bounds__(256) void k_pre2(
    const float* __restrict__ Wih2, const float* __restrict__ bih2,
    const float* __restrict__ bhh2)
{
    __shared__ __align__(16) float shW[HID * 129];
    __shared__ __align__(16) float4 shE[2][8][33];   // [group][row][float4 col]

    const int tid = threadIdx.x;
    const int g = tid >> 7;          // group 0/1
    const int j = tid & 127;         // feature

    // Stage Wih2 coalesced, padded stride 129 (conflict-free row copy).
    for (int it = 0; it < 64; ++it) {
        int f = it * 256 + tid;
        int row = f >> 7, col = f & 127;
        shW[row * 129 + col] = Wih2[f];
    }
    __syncthreads();

    float W[128];
#pragma unroll
    for (int i = 0; i < 128; ++i) W[i] = shW[j * 129 + i];
    const float bb = bih2[j] + bhh2[j];

    // Block handles 256 rows: group g covers rows [base + g*128, +128) in 16x8.
    const long base = (long)blockIdx.x * 256 + g * 128;
    const float4* __restrict__ o4 = (const float4*)g_out1;

    for (int it = 0; it < 16; ++it) {
        const long rid0 = base + it * 8;
        {   // stage 8 rows x 128 floats (32 float4 per row); 128 thr x 2 ld
            int rr = j >> 4, c = j & 15;
            shE[g][rr][c] = o4[(rid0 + rr) * 32 + c];
            shE[g][rr][c + 16] = o4[(rid0 + rr) * 32 + c + 16];
        }
        __syncthreads();

        float acc[8];
#pragma unroll
        for (int r = 0; r < 8; ++r) acc[r] = bb;
#pragma unroll
        for (int k4 = 0; k4 < 32; ++k4) {
#pragma unroll
            for (int r = 0; r < 8; ++r) {
                float4 e = shE[g][r][k4];
                acc[r] = fmaf(W[4 * k4 + 0], e.x, acc[r]);
                acc[r] = fmaf(W[4 * k4 + 1], e.y, acc[r]);
                acc[r] = fmaf(W[4 * k4 + 2], e.z, acc[r]);
                acc[r] = fmaf(W[4 * k4 + 3], e.w, acc[r]);
            }
        }
#pragma unroll
        for (int r = 0; r < 8; ++r)
            g_pre2[(rid0 + r) * HID + j] = acc[r];
        __syncthreads();
    }
}

// ---------------------------------------------------------------------------
// Kernel 4: layer-2 scan (same shape as scan1; no out1 stream, final h2 only).
//   h2_new = tanh(pre2[t] + W_hh2 . h2_old)
// ---------------------------------------------------------------------------
__global__ __launch_bounds__(256, 1) void k_scan2(
    const float* __restrict__ Whh2)
{
    __shared__ __align__(16) float h2s[2][2][HID];

    const int tid = threadIdx.x;
    const int r = tid >> 7;
    const int j = tid & 127;
    const int b = blockIdx.x * 2 + r;

    float W[128];
    {
        const float4* w4 = (const float4*)(Whh2 + j * HID);
#pragma unroll
        for (int i = 0; i < 32; ++i) {
            float4 a = w4[i];
            W[4 * i] = a.x; W[4 * i + 1] = a.y; W[4 * i + 2] = a.z; W[4 * i + 3] = a.w;
        }
    }

    h2s[0][r][j] = 0.f;
    h2s[1][r][j] = 0.f;
    __syncthreads();

    const float* preBase = g_pre2 + (long)b * HID + j;
    float pre_r = preBase[0];
    float h2n = 0.f;

    for (int t = 0; t < TT; ++t) {
        const int cur = t & 1, nxt = cur ^ 1;
        const float4* h = (const float4*)&h2s[cur][r][0];

        float acc = pre_r;
#pragma unroll
        for (int i = 0; i < 32; ++i) {
            float4 u = h[i];
            acc = fmaf(W[4 * i + 0], u.x, acc);
            acc = fmaf(W[4 * i + 1], u.y, acc);
            acc = fmaf(W[4 * i + 2], u.z, acc);
            acc = fmaf(W[4 * i + 3], u.w, acc);
        }
        h2n = fast_tanh(acc);
        h2s[nxt][r][j] = h2n;
        if (t + 1 < TT) pre_r = preBase[(long)(t + 1) * BB * HID];
        __syncthreads();
    }

    g_h2[b * HID + j] = h2n;
}

// ---------------------------------------------------------------------------
// Kernel 5: epilogue — LN -> proj -> tanh -> LN. One block per batch row.
// ---------------------------------------------------------------------------
__global__ __launch_bounds__(128) void k_epi(
    const float* __restrict__ ln_g, const float* __restrict__ ln_b,
    const float* __restrict__ projW, const float* __restrict__ proj_b,
    const float* __restrict__ on_g, const float* __restrict__ on_b,
    float* __restrict__ out)
{
    __shared__ __align__(16) float sh_rep[HID];
    __shared__ float sh_red[8];

    const int j = threadIdx.x;
    const int b = blockIdx.x;

    float v = g_h2[b * HID + j];

    float s = v, q = v * v;
#pragma unroll
    for (int o = 16; o; o >>= 1) {
        s += __shfl_xor_sync(0xffffffffu, s, o);
        q += __shfl_xor_sync(0xffffffffu, q, o);
    }
    if ((j & 31) == 0) { sh_red[j >> 5] = s; sh_red[4 + (j >> 5)] = q; }
    __syncthreads();
    s = sh_red[0] + sh_red[1] + sh_red[2] + sh_red[3];
    q = sh_red[4] + sh_red[5] + sh_red[6] + sh_red[7];
    float mu = s * (1.f / HID);
    float var = q * (1.f / HID) - mu * mu;
    float rep = (v - mu) * rsqrtf(var + 1e-5f) * ln_g[j] + ln_b[j];
    sh_rep[j] = rep;
    __syncthreads();

    float acc = proj_b[j];
    const float4* w4 = (const float4*)(projW + j * HID);
    const float4* r4 = (const float4*)sh_rep;
#pragma unroll
    for (int i = 0; i < 32; ++i) {
        float4 w = __ldg(&w4[i]);
        float4 r = r4[i];
        acc = fmaf(w.x, r.x, acc);
        acc = fmaf(w.y, r.y, acc);
        acc = fmaf(w.z, r.z, acc);
        acc = fmaf(w.w, r.w, acc);
    }
    float tv = tanhf(acc);

    __syncthreads();
    s = tv; q = tv * tv;
#pragma unroll
    for (int o = 16; o; o >>= 1) {
        s += __shfl_xor_sync(0xffffffffu, s, o);
        q += __shfl_xor_sync(0xffffffffu, q, o);
    }
    if ((j & 31) == 0) { sh_red[j >> 5] = s; sh_red[4 + (j >> 5)] = q; }
    __syncthreads();
    s = sh_red[0] + sh_red[1] + sh_red[2] + sh_red[3];
    q = sh_red[4] + sh_red[5] + sh_red[6] + sh_red[7];
    float mu2 = s * (1.f / HID);
    float var2 = q * (1.f / HID) - mu2 * mu2;
    out[b * HID + j] = (tv - mu2) * rsqrtf(var2 + 1e-5f) * on_g[j] + on_b[j];
}

// ---------------------------------------------------------------------------
extern "C" void kernel_launch(void* const* d_in, const int* in_sizes, int n_in,
                              void* d_out, int out_size)
{
    const int*   x     = (const int*)  d_in[0];
    const float* emb   = (const float*)d_in[1];
    const float* Wih1  = (const float*)d_in[2];
    const float* bih1  = (const float*)d_in[3];
    const float* Whh1  = (const float*)d_in[4];
    const float* bhh1  = (const float*)d_in[5];
    const float* Wih2  = (const float*)d_in[6];
    const float* bih2  = (const float*)d_in[7];
    const float* Whh2  = (const float*)d_in[8];
    const float* bhh2  = (const float*)d_in[9];
    const float* ln_g  = (const float*)d_in[10];
    const float* ln_b  = (const float*)d_in[11];
    const float* projW = (const float*)d_in[12];
    const float* projb = (const float*)d_in[13];
    const float* on_g  = (const float*)d_in[14];
    const float* on_b  = (const float*)d_in[15];

    k_pre1<<<512, 128>>>(x, emb, Wih1, bih1, bhh1);
    k_scan1<<<128, 256>>>(Whh1);
    k_pre2<<<512, 256>>>(Wih2, bih2, bhh2);
    k_scan2<<<128, 256>>>(Whh2);
    k_epi<<<256, 128>>>(ln_g, ln_b, projW, projb, on_g, on_b, (float*)d_out);
}